// round 2
// baseline (speedup 1.0000x reference)
#include <cuda_runtime.h>
#include <math.h>

#define BATCH 16
#define FH 192
#define FW 192
#define NA 9
#define NPI (FH*FW*NA)      /* 331776 anchors per image */
#define PRE 6000
#define POST 1000
#define CAP 16384           /* candidate capacity per image (power of two for bitonic) */
#define HB 65536            /* histogram buckets = top 16 bits of fp32 score */

// ---------------- device scratch (no allocations allowed) ----------------
__device__ unsigned int       g_hist[BATCH * HB];        // 4 MB
__device__ unsigned int       g_cnt[BATCH];
__device__ int                g_thresh[BATCH];
__device__ unsigned long long g_keys[BATCH * CAP];       // 2 MB
__device__ float4             g_boxes[BATCH * PRE];      // 384 KB

// ---------------- kernel 1: zero scratch (needed every graph replay) -----
__global__ void k_zero() {
    size_t i = (size_t)blockIdx.x * blockDim.x + threadIdx.x;
    size_t stride = (size_t)gridDim.x * blockDim.x;
    for (size_t j = i; j < (size_t)BATCH * HB; j += stride) g_hist[j] = 0u;
    for (size_t j = i; j < (size_t)BATCH * CAP; j += stride) g_keys[j] = 0ull;
    if (i < BATCH) g_cnt[i] = 0u;
}

// ---------------- kernel 2: score-bit histogram per image ----------------
__global__ void k_hist(const float* __restrict__ scores) {
    int total = BATCH * NPI;
    for (int i = blockIdx.x * blockDim.x + threadIdx.x; i < total;
         i += gridDim.x * blockDim.x) {
        unsigned bits = __float_as_uint(scores[i]);   // scores >= 0 -> bit order == value order
        int b = i / NPI;
        atomicAdd(&g_hist[b * HB + (bits >> 16)], 1u);
    }
}

// ---------------- kernel 3: per-image threshold bucket --------------------
// Largest bucket T such that count(bucket >= T) >= PRE.
__global__ void k_thresh() {
    int b = blockIdx.x;
    int t = threadIdx.x;               // 256 threads, each sums a 256-bucket chunk
    __shared__ unsigned csum[256];
    const unsigned* h = g_hist + (size_t)b * HB;
    unsigned s = 0;
    int hi = HB - t * 256;
    for (int i = hi - 256; i < hi; i++) s += h[i];
    csum[t] = s;
    __syncthreads();
    if (t == 0) {
        unsigned cum = 0;
        int T = 0;
        for (int c = 0; c < 256; c++) {
            if (cum + csum[c] >= PRE) {
                int hi2 = HB - c * 256;
                for (int i = hi2 - 1;; i--) {
                    cum += h[i];
                    if (cum >= PRE) { T = i; break; }
                }
                break;
            }
            cum += csum[c];
        }
        g_thresh[b] = T;
    }
}

// ---------------- kernel 4: collect candidate keys ------------------------
// key = (score_bits << 32) | (~idx): descending sort => score desc, then idx asc
// (matches lax.top_k stable tie-breaking exactly).
__global__ void k_collect(const float* __restrict__ scores) {
    int total = BATCH * NPI;
    for (int i = blockIdx.x * blockDim.x + threadIdx.x; i < total;
         i += gridDim.x * blockDim.x) {
        int b = i / NPI;
        int idx = i - b * NPI;
        unsigned bits = __float_as_uint(scores[i]);
        if ((int)(bits >> 16) >= g_thresh[b]) {
            unsigned pos = atomicAdd(&g_cnt[b], 1u);
            if (pos < CAP)
                g_keys[(size_t)b * CAP + pos] =
                    ((unsigned long long)bits << 32) |
                    (unsigned long long)(0xFFFFFFFFu - (unsigned)idx);
        }
    }
}

// ---------------- kernel 5: per-image bitonic sort + decode ---------------
__global__ void k_sort_decode(const float* __restrict__ deltas,
                              const float* __restrict__ banch) {
    extern __shared__ unsigned long long sk[];   // CAP u64 = 128 KB
    __shared__ float sbase[NA * 4];
    int b = blockIdx.x, tid = threadIdx.x, bs = blockDim.x;

    for (int i = tid; i < CAP; i += bs) sk[i] = g_keys[(size_t)b * CAP + i];
    if (tid < NA * 4) sbase[tid] = banch[tid];
    __syncthreads();

    // bitonic sort, descending
    for (int k = 2; k <= CAP; k <<= 1) {
        for (int j = k >> 1; j > 0; j >>= 1) {
            for (int i = tid; i < CAP; i += bs) {
                int ixj = i ^ j;
                if (ixj > i) {
                    unsigned long long a = sk[i], c = sk[ixj];
                    bool desc = ((i & k) == 0);
                    if (desc ? (a < c) : (a > c)) { sk[i] = c; sk[ixj] = a; }
                }
            }
            __syncthreads();
        }
    }

    // decode top PRE boxes (strict non-fused fp32 to track XLA rounding)
    for (int p = tid; p < PRE; p += bs) {
        unsigned long long key = sk[p];
        unsigned idx = 0xFFFFFFFFu - (unsigned)(key & 0xFFFFFFFFull);
        int a = idx % NA;
        int cell = idx / NA;
        int x = cell % FW;
        int y = cell / FW;
        float gy = __fdiv_rn((float)y + 0.5f, (float)FH);
        float gx = __fdiv_rn((float)x + 0.5f, (float)FW);
        float a0 = fminf(fmaxf(__fadd_rn(gy, sbase[a * 4 + 0]), 0.f), 1.f);
        float a1 = fminf(fmaxf(__fadd_rn(gx, sbase[a * 4 + 1]), 0.f), 1.f);
        float a2 = fminf(fmaxf(__fadd_rn(gy, sbase[a * 4 + 2]), 0.f), 1.f);
        float a3 = fminf(fmaxf(__fadd_rn(gx, sbase[a * 4 + 3]), 0.f), 1.f);
        const float* dp =
            deltas + ((((size_t)b * FH + y) * FW + x) * NA + a) * 4;
        float d0 = __fmul_rn(dp[0], 0.1f);
        float d1 = __fmul_rn(dp[1], 0.1f);
        float d2 = __fmul_rn(dp[2], 0.2f);
        float d3 = __fmul_rn(dp[3], 0.2f);
        float ah = __fsub_rn(a2, a0), aw = __fsub_rn(a3, a1);
        float acy = __fadd_rn(a0, __fmul_rn(0.5f, ah));
        float acx = __fadd_rn(a1, __fmul_rn(0.5f, aw));
        float eh = (float)exp((double)d2);   // correctly-rounded fp32 exp
        float ew = (float)exp((double)d3);
        float h = __fmul_rn(eh, ah);
        float w = __fmul_rn(ew, aw);
        float cy = __fadd_rn(__fmul_rn(d0, ah), acy);
        float cx = __fadd_rn(__fmul_rn(d1, aw), acx);
        float4 box;
        box.x = fminf(fmaxf(__fsub_rn(cy, __fmul_rn(0.5f, h)), 0.f), 1.f);
        box.y = fminf(fmaxf(__fsub_rn(cx, __fmul_rn(0.5f, w)), 0.f), 1.f);
        box.z = fminf(fmaxf(__fadd_rn(cy, __fmul_rn(0.5f, h)), 0.f), 1.f);
        box.w = fminf(fmaxf(__fadd_rn(cx, __fmul_rn(0.5f, w)), 0.f), 1.f);
        g_boxes[(size_t)b * PRE + p] = box;
    }
}

// ---------------- kernel 6: greedy NMS per image --------------------------
// Sorted order => argmax == first unsuppressed index; only j > sel can matter.
#define SM_BOXES 0
#define SM_AREA  (PRE * 16)            /* 96000 */
#define SM_SUPP  (SM_AREA + PRE * 4)   /* 120000 */
#define SM_TOTAL (SM_SUPP + PRE)       /* 126000 */

__global__ void k_nms(float* __restrict__ out) {
    extern __shared__ unsigned char sm[];
    float4* sb = (float4*)(sm + SM_BOXES);
    float* sarea = (float*)(sm + SM_AREA);
    unsigned char* supp = sm + SM_SUPP;
    int b = blockIdx.x, tid = threadIdx.x, bs = blockDim.x;

    for (int i = tid; i < PRE; i += bs) {
        float4 v = g_boxes[(size_t)b * PRE + i];
        sb[i] = v;
        sarea[i] = __fmul_rn(fmaxf(__fsub_rn(v.z, v.x), 0.f),
                             fmaxf(__fsub_rn(v.w, v.y), 0.f));
        supp[i] = 0;
    }
    __shared__ int s_sel, s_cursor;
    __shared__ float4 s_box;
    __shared__ float s_area;
    if (tid == 0) s_cursor = 0;
    __syncthreads();

    float4* orow = (float4*)(out + (size_t)b * POST * 4);
    int k;
    for (k = 0; k < POST; k++) {
        if (tid == 0) {
            int c = s_cursor;
            while (c < PRE && supp[c]) c++;
            if (c < PRE) {
                s_sel = c;
                s_box = sb[c];
                s_area = sarea[c];
                s_cursor = c + 1;
                orow[k] = sb[c];
            } else {
                s_sel = -1;
            }
        }
        __syncthreads();
        int sel = s_sel;
        if (sel < 0) break;
        float4 bi = s_box;
        float ai = s_area;
        for (int j = sel + 1 + tid; j < PRE; j += bs) {
            if (!supp[j]) {
                float4 bj = sb[j];
                float yy1 = fmaxf(bi.x, bj.x);
                float xx1 = fmaxf(bi.y, bj.y);
                float yy2 = fminf(bi.z, bj.z);
                float xx2 = fminf(bi.w, bj.w);
                float ih = fmaxf(__fsub_rn(yy2, yy1), 0.f);
                float iw = fmaxf(__fsub_rn(xx2, xx1), 0.f);
                float inter = __fmul_rn(ih, iw);
                float denom = __fadd_rn(
                    __fsub_rn(__fadd_rn(ai, sarea[j]), inter), 1e-8f);
                float iou = __fdiv_rn(inter, denom);
                if (iou > 0.7f) supp[j] = 1;
            }
        }
        __syncthreads();
    }
    // zero-pad remaining outputs (reference pads with zeros)
    for (int idx = k * 4 + tid; idx < POST * 4; idx += bs)
        out[(size_t)b * POST * 4 + idx] = 0.0f;
}

// ---------------- launch ---------------------------------------------------
extern "C" void kernel_launch(void* const* d_in, const int* in_sizes, int n_in,
                              void* d_out, int out_size) {
    const float* deltas = (const float*)d_in[0];   // (16,192,192,36)
    const float* scores = (const float*)d_in[1];   // (16,192,192,9)
    const float* banch  = (const float*)d_in[2];   // (9,4)
    float* out = (float*)d_out;                    // (16,1000,4)

    cudaFuncSetAttribute(k_sort_decode,
                         cudaFuncAttributeMaxDynamicSharedMemorySize,
                         CAP * (int)sizeof(unsigned long long));
    cudaFuncSetAttribute(k_nms,
                         cudaFuncAttributeMaxDynamicSharedMemorySize, SM_TOTAL);

    k_zero<<<2048, 256>>>();
    int total = BATCH * NPI;
    int blocks = (total + 255) / 256;
    k_hist<<<blocks, 256>>>(scores);
    k_thresh<<<BATCH, 256>>>();
    k_collect<<<blocks, 256>>>(scores);
    k_sort_decode<<<BATCH, 1024, CAP * (int)sizeof(unsigned long long)>>>(
        deltas, banch);
    k_nms<<<BATCH, 1024, SM_TOTAL>>>(out);
}

// round 3
// speedup vs baseline: 1.5417x; 1.5417x over previous
#include <cuda_runtime.h>
#include <math.h>

#define BATCH 16
#define FH 192
#define FW 192
#define NA 9
#define NPI (FH*FW*NA)      /* 331776 anchors per image */
#define PRE 6000
#define POST 1000
#define CAP 16384           /* candidate capacity per image (power of two for bitonic) */
#define HB 65536            /* histogram buckets = top 16 bits of fp32 score */
#define DEADID 0xFFFFu

// ---------------- device scratch (no allocations allowed) ----------------
__device__ unsigned int       g_hist[BATCH * HB];        // 4 MB
__device__ unsigned int       g_cnt[BATCH];
__device__ int                g_thresh[BATCH];
__device__ unsigned long long g_keys[BATCH * CAP];       // 2 MB
__device__ float4             g_boxes[BATCH * PRE];      // 384 KB

// ---------------- kernel 1: zero scratch (needed every graph replay) -----
__global__ void k_zero() {
    size_t i = (size_t)blockIdx.x * blockDim.x + threadIdx.x;
    size_t stride = (size_t)gridDim.x * blockDim.x;
    for (size_t j = i; j < (size_t)BATCH * HB; j += stride) g_hist[j] = 0u;
    for (size_t j = i; j < (size_t)BATCH * CAP; j += stride) g_keys[j] = 0ull;
    if (i < BATCH) g_cnt[i] = 0u;
}

// ---------------- kernel 2: score-bit histogram per image ----------------
__global__ void k_hist(const float* __restrict__ scores) {
    int total = BATCH * NPI;
    for (int i = blockIdx.x * blockDim.x + threadIdx.x; i < total;
         i += gridDim.x * blockDim.x) {
        unsigned bits = __float_as_uint(scores[i]);   // scores >= 0 -> bit order == value order
        int b = i / NPI;
        atomicAdd(&g_hist[b * HB + (bits >> 16)], 1u);
    }
}

// ---------------- kernel 3: per-image threshold bucket --------------------
// Largest bucket T such that count(bucket >= T) >= PRE.
__global__ void k_thresh() {
    int b = blockIdx.x;
    int t = threadIdx.x;               // 256 threads, each sums a 256-bucket chunk
    __shared__ unsigned csum[256];
    const unsigned* h = g_hist + (size_t)b * HB;
    unsigned s = 0;
    int hi = HB - t * 256;
    for (int i = hi - 256; i < hi; i++) s += h[i];
    csum[t] = s;
    __syncthreads();
    if (t == 0) {
        unsigned cum = 0;
        int T = 0;
        for (int c = 0; c < 256; c++) {
            if (cum + csum[c] >= PRE) {
                int hi2 = HB - c * 256;
                for (int i = hi2 - 1;; i--) {
                    cum += h[i];
                    if (cum >= PRE) { T = i; break; }
                }
                break;
            }
            cum += csum[c];
        }
        g_thresh[b] = T;
    }
}

// ---------------- kernel 4: collect candidate keys ------------------------
// key = (score_bits << 32) | (~idx): descending sort => score desc, then idx asc
// (matches lax.top_k stable tie-breaking exactly).
__global__ void k_collect(const float* __restrict__ scores) {
    int total = BATCH * NPI;
    for (int i = blockIdx.x * blockDim.x + threadIdx.x; i < total;
         i += gridDim.x * blockDim.x) {
        int b = i / NPI;
        int idx = i - b * NPI;
        unsigned bits = __float_as_uint(scores[i]);
        if ((int)(bits >> 16) >= g_thresh[b]) {
            unsigned pos = atomicAdd(&g_cnt[b], 1u);
            if (pos < CAP)
                g_keys[(size_t)b * CAP + pos] =
                    ((unsigned long long)bits << 32) |
                    (unsigned long long)(0xFFFFFFFFu - (unsigned)idx);
        }
    }
}

// ---------------- kernel 5: per-image bitonic sort + decode ---------------
__global__ void k_sort_decode(const float* __restrict__ deltas,
                              const float* __restrict__ banch) {
    extern __shared__ unsigned long long sk[];   // CAP u64 = 128 KB
    __shared__ float sbase[NA * 4];
    int b = blockIdx.x, tid = threadIdx.x, bs = blockDim.x;

    for (int i = tid; i < CAP; i += bs) sk[i] = g_keys[(size_t)b * CAP + i];
    if (tid < NA * 4) sbase[tid] = banch[tid];
    __syncthreads();

    // bitonic sort, descending
    for (int k = 2; k <= CAP; k <<= 1) {
        for (int j = k >> 1; j > 0; j >>= 1) {
            for (int i = tid; i < CAP; i += bs) {
                int ixj = i ^ j;
                if (ixj > i) {
                    unsigned long long a = sk[i], c = sk[ixj];
                    bool desc = ((i & k) == 0);
                    if (desc ? (a < c) : (a > c)) { sk[i] = c; sk[ixj] = a; }
                }
            }
            __syncthreads();
        }
    }

    // decode top PRE boxes (strict non-fused fp32 to track XLA rounding)
    for (int p = tid; p < PRE; p += bs) {
        unsigned long long key = sk[p];
        unsigned idx = 0xFFFFFFFFu - (unsigned)(key & 0xFFFFFFFFull);
        int a = idx % NA;
        int cell = idx / NA;
        int x = cell % FW;
        int y = cell / FW;
        float gy = __fdiv_rn((float)y + 0.5f, (float)FH);
        float gx = __fdiv_rn((float)x + 0.5f, (float)FW);
        float a0 = fminf(fmaxf(__fadd_rn(gy, sbase[a * 4 + 0]), 0.f), 1.f);
        float a1 = fminf(fmaxf(__fadd_rn(gx, sbase[a * 4 + 1]), 0.f), 1.f);
        float a2 = fminf(fmaxf(__fadd_rn(gy, sbase[a * 4 + 2]), 0.f), 1.f);
        float a3 = fminf(fmaxf(__fadd_rn(gx, sbase[a * 4 + 3]), 0.f), 1.f);
        const float* dp =
            deltas + ((((size_t)b * FH + y) * FW + x) * NA + a) * 4;
        float d0 = __fmul_rn(dp[0], 0.1f);
        float d1 = __fmul_rn(dp[1], 0.1f);
        float d2 = __fmul_rn(dp[2], 0.2f);
        float d3 = __fmul_rn(dp[3], 0.2f);
        float ah = __fsub_rn(a2, a0), aw = __fsub_rn(a3, a1);
        float acy = __fadd_rn(a0, __fmul_rn(0.5f, ah));
        float acx = __fadd_rn(a1, __fmul_rn(0.5f, aw));
        float eh = (float)exp((double)d2);   // correctly-rounded fp32 exp
        float ew = (float)exp((double)d3);
        float h = __fmul_rn(eh, ah);
        float w = __fmul_rn(ew, aw);
        float cy = __fadd_rn(__fmul_rn(d0, ah), acy);
        float cx = __fadd_rn(__fmul_rn(d1, aw), acx);
        float4 box;
        box.x = fminf(fmaxf(__fsub_rn(cy, __fmul_rn(0.5f, h)), 0.f), 1.f);
        box.y = fminf(fmaxf(__fsub_rn(cx, __fmul_rn(0.5f, w)), 0.f), 1.f);
        box.z = fminf(fmaxf(__fadd_rn(cy, __fmul_rn(0.5f, h)), 0.f), 1.f);
        box.w = fminf(fmaxf(__fadd_rn(cx, __fmul_rn(0.5f, w)), 0.f), 1.f);
        g_boxes[(size_t)b * PRE + p] = box;
    }
}

// ---------------- kernel 6: greedy NMS with compacted alive list ----------
// Shared layout: boxes 96000 | areas 24000 | list0 12000 | list1 12000
#define NMS_SM_AREA  96000
#define NMS_SM_LST0  120000
#define NMS_SM_LST1  132000
#define NMS_SM_TOTAL 144000

__global__ void k_nms(float* __restrict__ out) {
    extern __shared__ unsigned char sm[];
    float4* sb = (float4*)sm;
    float* sarea = (float*)(sm + NMS_SM_AREA);
    unsigned short* lst0 = (unsigned short*)(sm + NMS_SM_LST0);
    unsigned short* lst1 = (unsigned short*)(sm + NMS_SM_LST1);
    __shared__ int s_selpos, s_head, s_cnt, s_total;
    __shared__ float4 s_box;
    __shared__ float s_area;
    __shared__ int s_warp[32];

    int b = blockIdx.x, tid = threadIdx.x, bs = blockDim.x;
    for (int i = tid; i < PRE; i += bs) {
        float4 v = g_boxes[(size_t)b * PRE + i];
        sb[i] = v;
        sarea[i] = __fmul_rn(fmaxf(__fsub_rn(v.z, v.x), 0.f),
                             fmaxf(__fsub_rn(v.w, v.y), 0.f));
        lst0[i] = (unsigned short)i;
    }
    if (tid == 0) { s_head = 0; s_cnt = PRE; }
    int cur = 0;
    float4* orow4 = (float4*)(out + (size_t)b * POST * 4);
    __syncthreads();

    int k;
    for (k = 0; k < POST; k++) {
        unsigned short* lst = cur ? lst1 : lst0;
        if (tid == 0) {
            int h = s_head, c = s_cnt;
            while (h < c && lst[h] == DEADID) h++;
            if (h < c) {
                int id = lst[h];
                s_selpos = h;
                s_head = h + 1;
                float4 bx = sb[id];
                s_box = bx;
                s_area = sarea[id];
                orow4[k] = bx;
            } else {
                s_selpos = -1;
            }
        }
        __syncthreads();
        int selpos = s_selpos;
        if (selpos < 0) break;
        float4 bi = s_box;
        float ai = s_area;
        int cnt = s_cnt;

        for (int p = selpos + 1 + tid; p < cnt; p += bs) {
            unsigned short id = lst[p];
            if (id != DEADID) {
                float4 bj = sb[id];
                float yy1 = fmaxf(bi.x, bj.x);
                float xx1 = fmaxf(bi.y, bj.y);
                float yy2 = fminf(bi.z, bj.z);
                float xx2 = fminf(bi.w, bj.w);
                float ih = fmaxf(__fsub_rn(yy2, yy1), 0.f);
                float iw = fmaxf(__fsub_rn(xx2, xx1), 0.f);
                float inter = __fmul_rn(ih, iw);
                float denom = __fadd_rn(
                    __fsub_rn(__fadd_rn(ai, sarea[id]), inter), 1e-8f);
                // suppress <=> __fdiv_rn(inter, denom) > 0.7f
                // fast exact paths via banded multiply; rare exact fdiv fallback
                bool sup;
                if (inter > __fmul_rn(denom, 0.7000500f)) sup = true;
                else if (inter < __fmul_rn(denom, 0.6999500f)) sup = false;
                else sup = (__fdiv_rn(inter, denom) > 0.7f);
                if (sup) lst[p] = DEADID;
            }
        }

        if ((k & 31) == 31) {
            __syncthreads();   // suppression writes visible before compaction
            int head = s_head, c2 = s_cnt;
            int n = c2 - head;
            int per = (n + bs - 1) / bs;        // <= 6
            int st = head + tid * per;
            int en = st + per; if (en > c2) en = c2;
            unsigned short tmp[6];
            int c = 0;
            for (int p = st; p < en; p++) {
                unsigned short id = lst[p];
                if (id != DEADID) tmp[c++] = id;
            }
            // block-wide exclusive scan of c
            int lane = tid & 31, wid = tid >> 5;
            int incl = c;
            for (int d = 1; d < 32; d <<= 1) {
                int t = __shfl_up_sync(0xffffffffu, incl, d);
                if (lane >= d) incl += t;
            }
            if (lane == 31) s_warp[wid] = incl;
            __syncthreads();
            if (wid == 0) {
                int v = s_warp[lane];
                int wi = v;
                for (int d = 1; d < 32; d <<= 1) {
                    int t = __shfl_up_sync(0xffffffffu, wi, d);
                    if (lane >= d) wi += t;
                }
                s_warp[lane] = wi - v;          // exclusive warp offset
                if (lane == 31) s_total = wi;
            }
            __syncthreads();
            int off = s_warp[wid] + (incl - c);
            unsigned short* other = cur ? lst0 : lst1;
            for (int i2 = 0; i2 < c; i2++) other[off + i2] = tmp[i2];
            __syncthreads();
            if (tid == 0) { s_cnt = s_total; s_head = 0; }
            cur ^= 1;
            __syncthreads();
        } else {
            __syncthreads();
        }
    }
    // zero-pad remaining outputs (reference pads with zeros)
    for (int idx = k * 4 + tid; idx < POST * 4; idx += bs)
        out[(size_t)b * POST * 4 + idx] = 0.0f;
}

// ---------------- launch ---------------------------------------------------
extern "C" void kernel_launch(void* const* d_in, const int* in_sizes, int n_in,
                              void* d_out, int out_size) {
    const float* deltas = (const float*)d_in[0];   // (16,192,192,36)
    const float* scores = (const float*)d_in[1];   // (16,192,192,9)
    const float* banch  = (const float*)d_in[2];   // (9,4)
    float* out = (float*)d_out;                    // (16,1000,4)

    cudaFuncSetAttribute(k_sort_decode,
                         cudaFuncAttributeMaxDynamicSharedMemorySize,
                         CAP * (int)sizeof(unsigned long long));
    cudaFuncSetAttribute(k_nms,
                         cudaFuncAttributeMaxDynamicSharedMemorySize,
                         NMS_SM_TOTAL);

    k_zero<<<2048, 256>>>();
    int total = BATCH * NPI;
    int blocks = (total + 255) / 256;
    k_hist<<<blocks, 256>>>(scores);
    k_thresh<<<BATCH, 256>>>();
    k_collect<<<blocks, 256>>>(scores);
    k_sort_decode<<<BATCH, 1024, CAP * (int)sizeof(unsigned long long)>>>(
        deltas, banch);
    k_nms<<<BATCH, 1024, NMS_SM_TOTAL>>>(out);
}

// round 4
// speedup vs baseline: 1.5478x; 1.0039x over previous
#include <cuda_runtime.h>
#include <math.h>

#define BATCH 16
#define FH 192
#define FW 192
#define NA 9
#define NPI (FH*FW*NA)      /* 331776 anchors per image */
#define PRE 6000
#define POST 1000
#define CAP 16384           /* candidate capacity per image (power of two for bitonic) */
#define HB 65536            /* histogram buckets = top 16 bits of fp32 score */
#define DEADID 0xFFFFu

// ---------------- device scratch (no allocations allowed) ----------------
__device__ unsigned int       g_hist[BATCH * HB];        // 4 MB
__device__ unsigned int       g_cnt[BATCH];
__device__ int                g_thresh[BATCH];
__device__ unsigned long long g_keys[BATCH * CAP];       // 2 MB
__device__ float4             g_boxes[BATCH * PRE];      // 384 KB

// ---------------- kernel 1: zero scratch (needed every graph replay) -----
__global__ void k_zero() {
    size_t i = (size_t)blockIdx.x * blockDim.x + threadIdx.x;
    size_t stride = (size_t)gridDim.x * blockDim.x;
    for (size_t j = i; j < (size_t)BATCH * HB; j += stride) g_hist[j] = 0u;
    for (size_t j = i; j < (size_t)BATCH * CAP; j += stride) g_keys[j] = 0ull;
    if (i < BATCH) g_cnt[i] = 0u;
}

// ---------------- kernel 2: score-bit histogram per image ----------------
__global__ void k_hist(const float* __restrict__ scores) {
    int total = BATCH * NPI;
    for (int i = blockIdx.x * blockDim.x + threadIdx.x; i < total;
         i += gridDim.x * blockDim.x) {
        unsigned bits = __float_as_uint(scores[i]);   // scores >= 0 -> bit order == value order
        int b = i / NPI;
        atomicAdd(&g_hist[b * HB + (bits >> 16)], 1u);
    }
}

// ---------------- kernel 3: per-image threshold bucket --------------------
// Largest bucket T such that count(bucket >= T) >= PRE.
__global__ void k_thresh() {
    int b = blockIdx.x;
    int t = threadIdx.x;               // 256 threads, each sums a 256-bucket chunk
    __shared__ unsigned csum[256];
    const unsigned* h = g_hist + (size_t)b * HB;
    unsigned s = 0;
    int hi = HB - t * 256;
    for (int i = hi - 256; i < hi; i++) s += h[i];
    csum[t] = s;
    __syncthreads();
    if (t == 0) {
        unsigned cum = 0;
        int T = 0;
        for (int c = 0; c < 256; c++) {
            if (cum + csum[c] >= PRE) {
                int hi2 = HB - c * 256;
                for (int i = hi2 - 1;; i--) {
                    cum += h[i];
                    if (cum >= PRE) { T = i; break; }
                }
                break;
            }
            cum += csum[c];
        }
        g_thresh[b] = T;
    }
}

// ---------------- kernel 4: collect candidate keys ------------------------
// key = (score_bits << 32) | (~idx): descending sort => score desc, then idx asc
// (matches lax.top_k stable tie-breaking exactly).
__global__ void k_collect(const float* __restrict__ scores) {
    int total = BATCH * NPI;
    for (int i = blockIdx.x * blockDim.x + threadIdx.x; i < total;
         i += gridDim.x * blockDim.x) {
        int b = i / NPI;
        int idx = i - b * NPI;
        unsigned bits = __float_as_uint(scores[i]);
        if ((int)(bits >> 16) >= g_thresh[b]) {
            unsigned pos = atomicAdd(&g_cnt[b], 1u);
            if (pos < CAP)
                g_keys[(size_t)b * CAP + pos] =
                    ((unsigned long long)bits << 32) |
                    (unsigned long long)(0xFFFFFFFFu - (unsigned)idx);
        }
    }
}

// ---------------- kernel 5: per-image bitonic sort + decode ---------------
__global__ void k_sort_decode(const float* __restrict__ deltas,
                              const float* __restrict__ banch) {
    extern __shared__ unsigned long long sk[];   // CAP u64 = 128 KB
    __shared__ float sbase[NA * 4];
    int b = blockIdx.x, tid = threadIdx.x, bs = blockDim.x;

    for (int i = tid; i < CAP; i += bs) sk[i] = g_keys[(size_t)b * CAP + i];
    if (tid < NA * 4) sbase[tid] = banch[tid];
    __syncthreads();

    // bitonic sort, descending
    for (int k = 2; k <= CAP; k <<= 1) {
        for (int j = k >> 1; j > 0; j >>= 1) {
            for (int i = tid; i < CAP; i += bs) {
                int ixj = i ^ j;
                if (ixj > i) {
                    unsigned long long a = sk[i], c = sk[ixj];
                    bool desc = ((i & k) == 0);
                    if (desc ? (a < c) : (a > c)) { sk[i] = c; sk[ixj] = a; }
                }
            }
            __syncthreads();
        }
    }

    // decode top PRE boxes (strict non-fused fp32 to track XLA rounding)
    for (int p = tid; p < PRE; p += bs) {
        unsigned long long key = sk[p];
        unsigned idx = 0xFFFFFFFFu - (unsigned)(key & 0xFFFFFFFFull);
        int a = idx % NA;
        int cell = idx / NA;
        int x = cell % FW;
        int y = cell / FW;
        float gy = __fdiv_rn((float)y + 0.5f, (float)FH);
        float gx = __fdiv_rn((float)x + 0.5f, (float)FW);
        float a0 = fminf(fmaxf(__fadd_rn(gy, sbase[a * 4 + 0]), 0.f), 1.f);
        float a1 = fminf(fmaxf(__fadd_rn(gx, sbase[a * 4 + 1]), 0.f), 1.f);
        float a2 = fminf(fmaxf(__fadd_rn(gy, sbase[a * 4 + 2]), 0.f), 1.f);
        float a3 = fminf(fmaxf(__fadd_rn(gx, sbase[a * 4 + 3]), 0.f), 1.f);
        const float* dp =
            deltas + ((((size_t)b * FH + y) * FW + x) * NA + a) * 4;
        float d0 = __fmul_rn(dp[0], 0.1f);
        float d1 = __fmul_rn(dp[1], 0.1f);
        float d2 = __fmul_rn(dp[2], 0.2f);
        float d3 = __fmul_rn(dp[3], 0.2f);
        float ah = __fsub_rn(a2, a0), aw = __fsub_rn(a3, a1);
        float acy = __fadd_rn(a0, __fmul_rn(0.5f, ah));
        float acx = __fadd_rn(a1, __fmul_rn(0.5f, aw));
        float eh = (float)exp((double)d2);   // correctly-rounded fp32 exp
        float ew = (float)exp((double)d3);
        float h = __fmul_rn(eh, ah);
        float w = __fmul_rn(ew, aw);
        float cy = __fadd_rn(__fmul_rn(d0, ah), acy);
        float cx = __fadd_rn(__fmul_rn(d1, aw), acx);
        float4 box;
        box.x = fminf(fmaxf(__fsub_rn(cy, __fmul_rn(0.5f, h)), 0.f), 1.f);
        box.y = fminf(fmaxf(__fsub_rn(cx, __fmul_rn(0.5f, w)), 0.f), 1.f);
        box.z = fminf(fmaxf(__fadd_rn(cy, __fmul_rn(0.5f, h)), 0.f), 1.f);
        box.w = fminf(fmaxf(__fadd_rn(cx, __fmul_rn(0.5f, w)), 0.f), 1.f);
        g_boxes[(size_t)b * PRE + p] = box;
    }
}

// ---------------- kernel 6: greedy NMS with compacted alive list ----------
// Shared layout: boxes 96000 | areas 24000 | list0 12000 | list1 12000
#define NMS_SM_AREA  96000
#define NMS_SM_LST0  120000
#define NMS_SM_LST1  132000
#define NMS_SM_TOTAL 144000

__global__ void k_nms(float* __restrict__ out) {
    extern __shared__ unsigned char sm[];
    float4* sb = (float4*)sm;
    float* sarea = (float*)(sm + NMS_SM_AREA);
    unsigned short* lst0 = (unsigned short*)(sm + NMS_SM_LST0);
    unsigned short* lst1 = (unsigned short*)(sm + NMS_SM_LST1);
    __shared__ int s_selpos, s_head, s_cnt, s_total;
    __shared__ float4 s_box;
    __shared__ float s_area;
    __shared__ int s_warp[32];

    int b = blockIdx.x, tid = threadIdx.x, bs = blockDim.x;
    for (int i = tid; i < PRE; i += bs) {
        float4 v = g_boxes[(size_t)b * PRE + i];
        sb[i] = v;
        sarea[i] = __fmul_rn(fmaxf(__fsub_rn(v.z, v.x), 0.f),
                             fmaxf(__fsub_rn(v.w, v.y), 0.f));
        lst0[i] = (unsigned short)i;
    }
    if (tid == 0) { s_head = 0; s_cnt = PRE; }
    int cur = 0;
    float4* orow4 = (float4*)(out + (size_t)b * POST * 4);
    __syncthreads();

    int k;
    for (k = 0; k < POST; k++) {
        unsigned short* lst = cur ? lst1 : lst0;
        if (tid == 0) {
            int h = s_head, c = s_cnt;
            while (h < c && lst[h] == DEADID) h++;
            if (h < c) {
                int id = lst[h];
                s_selpos = h;
                s_head = h + 1;
                float4 bx = sb[id];
                s_box = bx;
                s_area = sarea[id];
                orow4[k] = bx;
            } else {
                s_selpos = -1;
            }
        }
        __syncthreads();
        int selpos = s_selpos;
        if (selpos < 0) break;
        float4 bi = s_box;
        float ai = s_area;
        int cnt = s_cnt;

        for (int p = selpos + 1 + tid; p < cnt; p += bs) {
            unsigned short id = lst[p];
            if (id != DEADID) {
                float4 bj = sb[id];
                float yy1 = fmaxf(bi.x, bj.x);
                float xx1 = fmaxf(bi.y, bj.y);
                float yy2 = fminf(bi.z, bj.z);
                float xx2 = fminf(bi.w, bj.w);
                float ih = fmaxf(__fsub_rn(yy2, yy1), 0.f);
                float iw = fmaxf(__fsub_rn(xx2, xx1), 0.f);
                float inter = __fmul_rn(ih, iw);
                float denom = __fadd_rn(
                    __fsub_rn(__fadd_rn(ai, sarea[id]), inter), 1e-8f);
                // suppress <=> __fdiv_rn(inter, denom) > 0.7f
                // fast exact paths via banded multiply; rare exact fdiv fallback
                bool sup;
                if (inter > __fmul_rn(denom, 0.7000500f)) sup = true;
                else if (inter < __fmul_rn(denom, 0.6999500f)) sup = false;
                else sup = (__fdiv_rn(inter, denom) > 0.7f);
                if (sup) lst[p] = DEADID;
            }
        }

        if ((k & 31) == 31) {
            __syncthreads();   // suppression writes visible before compaction
            int head = s_head, c2 = s_cnt;
            int n = c2 - head;
            int per = (n + bs - 1) / bs;        // <= 6
            int st = head + tid * per;
            int en = st + per; if (en > c2) en = c2;
            unsigned short tmp[6];
            int c = 0;
            for (int p = st; p < en; p++) {
                unsigned short id = lst[p];
                if (id != DEADID) tmp[c++] = id;
            }
            // block-wide exclusive scan of c
            int lane = tid & 31, wid = tid >> 5;
            int incl = c;
            for (int d = 1; d < 32; d <<= 1) {
                int t = __shfl_up_sync(0xffffffffu, incl, d);
                if (lane >= d) incl += t;
            }
            if (lane == 31) s_warp[wid] = incl;
            __syncthreads();
            if (wid == 0) {
                int v = s_warp[lane];
                int wi = v;
                for (int d = 1; d < 32; d <<= 1) {
                    int t = __shfl_up_sync(0xffffffffu, wi, d);
                    if (lane >= d) wi += t;
                }
                s_warp[lane] = wi - v;          // exclusive warp offset
                if (lane == 31) s_total = wi;
            }
            __syncthreads();
            int off = s_warp[wid] + (incl - c);
            unsigned short* other = cur ? lst0 : lst1;
            for (int i2 = 0; i2 < c; i2++) other[off + i2] = tmp[i2];
            __syncthreads();
            if (tid == 0) { s_cnt = s_total; s_head = 0; }
            cur ^= 1;
            __syncthreads();
        } else {
            __syncthreads();
        }
    }
    // zero-pad remaining outputs (reference pads with zeros)
    for (int idx = k * 4 + tid; idx < POST * 4; idx += bs)
        out[(size_t)b * POST * 4 + idx] = 0.0f;
}

// ---------------- launch ---------------------------------------------------
extern "C" void kernel_launch(void* const* d_in, const int* in_sizes, int n_in,
                              void* d_out, int out_size) {
    const float* deltas = (const float*)d_in[0];   // (16,192,192,36)
    const float* scores = (const float*)d_in[1];   // (16,192,192,9)
    const float* banch  = (const float*)d_in[2];   // (9,4)
    float* out = (float*)d_out;                    // (16,1000,4)

    cudaFuncSetAttribute(k_sort_decode,
                         cudaFuncAttributeMaxDynamicSharedMemorySize,
                         CAP * (int)sizeof(unsigned long long));
    cudaFuncSetAttribute(k_nms,
                         cudaFuncAttributeMaxDynamicSharedMemorySize,
                         NMS_SM_TOTAL);

    k_zero<<<2048, 256>>>();
    int total = BATCH * NPI;
    int blocks = (total + 255) / 256;
    k_hist<<<blocks, 256>>>(scores);
    k_thresh<<<BATCH, 256>>>();
    k_collect<<<blocks, 256>>>(scores);
    k_sort_decode<<<BATCH, 1024, CAP * (int)sizeof(unsigned long long)>>>(
        deltas, banch);
    k_nms<<<BATCH, 1024, NMS_SM_TOTAL>>>(out);
}

// round 5
// speedup vs baseline: 2.3405x; 1.5121x over previous
#include <cuda_runtime.h>
#include <math.h>

#define BATCH 16
#define FH 192
#define FW 192
#define NA 9
#define NPI (FH*FW*NA)      /* 331776 anchors per image */
#define NPI4 (NPI/4)
#define PRE 6000
#define POST 1000
#define CAP 16384           /* candidate capacity per image (power of two for bitonic) */
#define HB 65536            /* histogram buckets = top 16 bits of fp32 score */
#define DEADID 0xFFFFu

// ---------------- device scratch (no allocations allowed) ----------------
__device__ unsigned int       g_hist[BATCH * HB];        // 4 MB (zeroed by k_thresh each pass)
__device__ unsigned int       g_cnt[BATCH];
__device__ int                g_thresh[BATCH];
__device__ unsigned long long g_keys[BATCH * CAP];       // 2 MB
__device__ float4             g_boxes[BATCH * PRE];      // 384 KB

// ---------------- kernel 1: score-bit histogram per image -----------------
__global__ void k_hist(const float* __restrict__ scores) {
    int b = blockIdx.y;
    const float4* s4 = (const float4*)(scores + (size_t)b * NPI);
    unsigned* h = g_hist + (size_t)b * HB;
    for (int i = blockIdx.x * blockDim.x + threadIdx.x; i < NPI4;
         i += gridDim.x * blockDim.x) {
        float4 v = s4[i];
        atomicAdd(&h[__float_as_uint(v.x) >> 16], 1u);
        atomicAdd(&h[__float_as_uint(v.y) >> 16], 1u);
        atomicAdd(&h[__float_as_uint(v.z) >> 16], 1u);
        atomicAdd(&h[__float_as_uint(v.w) >> 16], 1u);
    }
}

// ---------------- kernel 2: per-image threshold bucket + scratch reset ----
// Largest bucket T such that count(bucket >= T) >= PRE. Then zero hist/cnt
// for the next graph replay (runs before k_collect in the same replay).
__global__ void k_thresh() {
    int b = blockIdx.x;
    int t = threadIdx.x;               // 256 threads, each sums a 256-bucket chunk
    __shared__ unsigned csum[256];
    unsigned* h = g_hist + (size_t)b * HB;
    unsigned s = 0;
    int hi = HB - t * 256;
    for (int i = hi - 256; i < hi; i++) s += h[i];
    csum[t] = s;
    __syncthreads();
    if (t == 0) {
        unsigned cum = 0;
        int T = 0;
        for (int c = 0; c < 256; c++) {
            if (cum + csum[c] >= PRE) {
                int hi2 = HB - c * 256;
                for (int i = hi2 - 1;; i--) {
                    cum += h[i];
                    if (cum >= PRE) { T = i; break; }
                }
                break;
            }
            cum += csum[c];
        }
        g_thresh[b] = T;
        g_cnt[b] = 0u;                 // reset candidate counter for k_collect
    }
    __syncthreads();
    // zero this image's histogram for the next replay
    for (int i = t; i < HB; i += 256) h[i] = 0u;
}

// ---------------- kernel 3: collect candidate keys ------------------------
// key = (score_bits << 32) | (~idx): descending sort => score desc, then idx asc
// (matches lax.top_k stable tie-breaking exactly).
__global__ void k_collect(const float* __restrict__ scores) {
    int b = blockIdx.y;
    const float4* s4 = (const float4*)(scores + (size_t)b * NPI);
    int T = g_thresh[b];
    for (int i = blockIdx.x * blockDim.x + threadIdx.x; i < NPI4;
         i += gridDim.x * blockDim.x) {
        float4 v = s4[i];
        unsigned bw[4] = {__float_as_uint(v.x), __float_as_uint(v.y),
                          __float_as_uint(v.z), __float_as_uint(v.w)};
#pragma unroll
        for (int c = 0; c < 4; c++) {
            if ((int)(bw[c] >> 16) >= T) {
                unsigned pos = atomicAdd(&g_cnt[b], 1u);
                if (pos < CAP) {
                    unsigned idx = 4u * (unsigned)i + (unsigned)c;
                    g_keys[(size_t)b * CAP + pos] =
                        ((unsigned long long)bw[c] << 32) |
                        (unsigned long long)(0xFFFFFFFFu - idx);
                }
            }
        }
    }
}

// ---------------- kernel 4: per-image bitonic sort + decode ---------------
__global__ void k_sort_decode(const float* __restrict__ deltas,
                              const float* __restrict__ banch) {
    extern __shared__ unsigned long long sk[];   // CAP u64 = 128 KB
    __shared__ float sbase[NA * 4];
    int b = blockIdx.x, tid = threadIdx.x, bs = blockDim.x;

    unsigned cnt = g_cnt[b];
    if (cnt > CAP) cnt = CAP;
    for (int i = tid; i < CAP; i += bs)
        sk[i] = ((unsigned)i < cnt) ? g_keys[(size_t)b * CAP + i] : 0ull;
    if (tid < NA * 4) sbase[tid] = banch[tid];
    __syncthreads();

    // bitonic sort, descending
    for (int k = 2; k <= CAP; k <<= 1) {
        for (int j = k >> 1; j > 0; j >>= 1) {
            for (int i = tid; i < CAP; i += bs) {
                int ixj = i ^ j;
                if (ixj > i) {
                    unsigned long long a = sk[i], c = sk[ixj];
                    bool desc = ((i & k) == 0);
                    if (desc ? (a < c) : (a > c)) { sk[i] = c; sk[ixj] = a; }
                }
            }
            __syncthreads();
        }
    }

    // decode top PRE boxes (strict non-fused fp32 to track XLA rounding)
    for (int p = tid; p < PRE; p += bs) {
        unsigned long long key = sk[p];
        unsigned idx = 0xFFFFFFFFu - (unsigned)(key & 0xFFFFFFFFull);
        int a = idx % NA;
        int cell = idx / NA;
        int x = cell % FW;
        int y = cell / FW;
        float gy = __fdiv_rn((float)y + 0.5f, (float)FH);
        float gx = __fdiv_rn((float)x + 0.5f, (float)FW);
        float a0 = fminf(fmaxf(__fadd_rn(gy, sbase[a * 4 + 0]), 0.f), 1.f);
        float a1 = fminf(fmaxf(__fadd_rn(gx, sbase[a * 4 + 1]), 0.f), 1.f);
        float a2 = fminf(fmaxf(__fadd_rn(gy, sbase[a * 4 + 2]), 0.f), 1.f);
        float a3 = fminf(fmaxf(__fadd_rn(gx, sbase[a * 4 + 3]), 0.f), 1.f);
        const float* dp =
            deltas + ((((size_t)b * FH + y) * FW + x) * NA + a) * 4;
        float d0 = __fmul_rn(dp[0], 0.1f);
        float d1 = __fmul_rn(dp[1], 0.1f);
        float d2 = __fmul_rn(dp[2], 0.2f);
        float d3 = __fmul_rn(dp[3], 0.2f);
        float ah = __fsub_rn(a2, a0), aw = __fsub_rn(a3, a1);
        float acy = __fadd_rn(a0, __fmul_rn(0.5f, ah));
        float acx = __fadd_rn(a1, __fmul_rn(0.5f, aw));
        float eh = (float)exp((double)d2);   // correctly-rounded fp32 exp
        float ew = (float)exp((double)d3);
        float h = __fmul_rn(eh, ah);
        float w = __fmul_rn(ew, aw);
        float cy = __fadd_rn(__fmul_rn(d0, ah), acy);
        float cx = __fadd_rn(__fmul_rn(d1, aw), acx);
        float4 box;
        box.x = fminf(fmaxf(__fsub_rn(cy, __fmul_rn(0.5f, h)), 0.f), 1.f);
        box.y = fminf(fmaxf(__fsub_rn(cx, __fmul_rn(0.5f, w)), 0.f), 1.f);
        box.z = fminf(fmaxf(__fadd_rn(cy, __fmul_rn(0.5f, h)), 0.f), 1.f);
        box.w = fminf(fmaxf(__fadd_rn(cx, __fmul_rn(0.5f, w)), 0.f), 1.f);
        g_boxes[(size_t)b * PRE + p] = box;
    }
}

// ---------------- kernel 5: multi-select greedy NMS -----------------------
// Per round: one warp chain-selects up to 32 boxes (exact greedy order: a
// candidate is selected iff not suppressed by any in-round prior selection;
// all earlier-round suppressions are already applied to the list). Then one
// bulk sweep suppresses the remaining list against all new selections, and
// one compaction rebuilds the alive list. ~32 rounds instead of 1000.
#define NMS_SM_AREA  96000
#define NMS_SM_LST0  120000
#define NMS_SM_LST1  132000
#define NMS_SM_TOTAL 144000

// suppress <=> __fdiv_rn(inter, denom) > 0.7f; banded multiply gives the
// exact answer outside a +-7e-5 relative band (>> 1ulp of mul/div), rare
// exact fdiv fallback inside the band.
__device__ __forceinline__ bool iou_sup(float4 bi, float ai, float4 bj, float aj) {
    float yy1 = fmaxf(bi.x, bj.x);
    float xx1 = fmaxf(bi.y, bj.y);
    float yy2 = fminf(bi.z, bj.z);
    float xx2 = fminf(bi.w, bj.w);
    float ih = fmaxf(__fsub_rn(yy2, yy1), 0.f);
    float iw = fmaxf(__fsub_rn(xx2, xx1), 0.f);
    float inter = __fmul_rn(ih, iw);
    float denom = __fadd_rn(__fsub_rn(__fadd_rn(ai, aj), inter), 1e-8f);
    if (inter > __fmul_rn(denom, 0.7000500f)) return true;
    if (inter < __fmul_rn(denom, 0.6999500f)) return false;
    return __fdiv_rn(inter, denom) > 0.7f;
}

__global__ void k_nms(float* __restrict__ out) {
    extern __shared__ unsigned char sm[];
    float4* sb = (float4*)sm;
    float* sarea = (float*)(sm + NMS_SM_AREA);
    unsigned short* lst0 = (unsigned short*)(sm + NMS_SM_LST0);
    unsigned short* lst1 = (unsigned short*)(sm + NMS_SM_LST1);
    __shared__ float4 ssel[32];
    __shared__ float  sselarea[32];
    __shared__ int s_nsel, s_walk, s_cnt, s_total;
    __shared__ int s_warp[32];

    int b = blockIdx.x, tid = threadIdx.x, bs = blockDim.x;
    for (int i = tid; i < PRE; i += bs) {
        float4 v = g_boxes[(size_t)b * PRE + i];
        sb[i] = v;
        sarea[i] = __fmul_rn(fmaxf(__fsub_rn(v.z, v.x), 0.f),
                             fmaxf(__fsub_rn(v.w, v.y), 0.f));
        lst0[i] = (unsigned short)i;
    }
    if (tid == 0) s_cnt = PRE;
    int cur = 0;
    float4* orow4 = (float4*)(out + (size_t)b * POST * 4);
    __syncthreads();

    int k = 0;
    while (k < POST) {
        unsigned short* lst = cur ? lst1 : lst0;
        // ---- phase A: warp 0 chain-selects up to min(32, POST-k) boxes ----
        if (tid < 32) {
            int lane = tid;
            int cnt = s_cnt;
            int lim = POST - k; if (lim > 32) lim = 32;
            int nsel = 0, p = 0;
            while (nsel < lim && p < cnt) {
                int id = lst[p];
                float4 bj = sb[id];
                float aj = sarea[id];
                bool sup = false;
                if (lane < nsel)
                    sup = iou_sup(ssel[lane], sselarea[lane], bj, aj);
                unsigned m = __ballot_sync(0xffffffffu, sup);
                if (m == 0) {
                    if (lane == 0) {
                        ssel[nsel] = bj;
                        sselarea[nsel] = aj;
                        orow4[k + nsel] = bj;
                        lst[p] = DEADID;
                    }
                    nsel++;
                } else {
                    if (lane == 0) lst[p] = DEADID;
                }
                __syncwarp();
                p++;
            }
            if (lane == 0) { s_nsel = nsel; s_walk = p; }
        }
        __syncthreads();
        int nsel = s_nsel;
        if (nsel == 0) break;
        int cnt = s_cnt;
        int walk = s_walk;

        // ---- phase B: bulk sweep remaining list vs all new selections ----
        for (int p = walk + tid; p < cnt; p += bs) {
            int id = lst[p];
            float4 bj = sb[id];
            float aj = sarea[id];
            bool dead = false;
            for (int s = 0; s < nsel; s++) {
                if (iou_sup(ssel[s], sselarea[s], bj, aj)) { dead = true; break; }
            }
            if (dead) lst[p] = DEADID;
        }
        __syncthreads();

        // ---- phase C: compact alive ids into the other buffer ----
        {
            int per = (cnt + bs - 1) / bs;          // <= 6
            int st = tid * per;
            int en = st + per; if (en > cnt) en = cnt;
            unsigned short tmp[6];
            int c = 0;
            for (int p = st; p < en; p++) {
                unsigned short id = lst[p];
                if (id != DEADID) tmp[c++] = id;
            }
            int lane = tid & 31, wid = tid >> 5;
            int incl = c;
            for (int d = 1; d < 32; d <<= 1) {
                int t = __shfl_up_sync(0xffffffffu, incl, d);
                if (lane >= d) incl += t;
            }
            if (lane == 31) s_warp[wid] = incl;
            __syncthreads();
            if (wid == 0) {
                int v = s_warp[lane];
                int wi = v;
                for (int d = 1; d < 32; d <<= 1) {
                    int t = __shfl_up_sync(0xffffffffu, wi, d);
                    if (lane >= d) wi += t;
                }
                s_warp[lane] = wi - v;              // exclusive warp offset
                if (lane == 31) s_total = wi;
            }
            __syncthreads();
            int off = s_warp[wid] + (incl - c);
            unsigned short* dst = cur ? lst0 : lst1;
            for (int i2 = 0; i2 < c; i2++) dst[off + i2] = tmp[i2];
            __syncthreads();
            if (tid == 0) s_cnt = s_total;
            cur ^= 1;
            __syncthreads();
        }
        k += nsel;
    }
    // zero-pad remaining outputs (reference pads with zeros)
    for (int idx = k * 4 + tid; idx < POST * 4; idx += bs)
        out[(size_t)b * POST * 4 + idx] = 0.0f;
}

// ---------------- launch ---------------------------------------------------
extern "C" void kernel_launch(void* const* d_in, const int* in_sizes, int n_in,
                              void* d_out, int out_size) {
    const float* deltas = (const float*)d_in[0];   // (16,192,192,36)
    const float* scores = (const float*)d_in[1];   // (16,192,192,9)
    const float* banch  = (const float*)d_in[2];   // (9,4)
    float* out = (float*)d_out;                    // (16,1000,4)

    cudaFuncSetAttribute(k_sort_decode,
                         cudaFuncAttributeMaxDynamicSharedMemorySize,
                         CAP * (int)sizeof(unsigned long long));
    cudaFuncSetAttribute(k_nms,
                         cudaFuncAttributeMaxDynamicSharedMemorySize,
                         NMS_SM_TOTAL);

    dim3 grid2(108, BATCH);                         // ~3 float4 per thread
    k_hist<<<grid2, 256>>>(scores);
    k_thresh<<<BATCH, 256>>>();
    k_collect<<<grid2, 256>>>(scores);
    k_sort_decode<<<BATCH, 1024, CAP * (int)sizeof(unsigned long long)>>>(
        deltas, banch);
    k_nms<<<BATCH, 1024, NMS_SM_TOTAL>>>(out);
}